// round 11
// baseline (speedup 1.0000x reference)
#include <cuda_runtime.h>
#include <math.h>
#include <stdint.h>

#define RUNS 512
#define WAYS 5
#define SHOT 5
#define NSUP 25
#define NQ   75
#define NF   100
#define NTOT 105
#define DIM  640
#define LAM  10.0f
#define ALPHA_ 0.7f
#define EPSV 1e-3f
#define MAXIT 1000

// ---------------- device scratch (static: no allocations allowed) ----------
__device__ float g_proto[RUNS][WAYS][DIM];
__device__ float g_Fp[RUNS][WAYS][DIM];     // masked proto rows (epoch 2)
__device__ float g_P1[RUNS][NQ][WAYS];      // sinkhorn1 state after pass-1
__device__ int   g_b1A[RUNS];               // per-run body counts (double buf)
__device__ int   g_b1B[RUNS];
__device__ float g_Zext[RUNS][NTOT][WAYS];  // extended Z (epoch 2, pre-solve)
__device__ float g_Z0[RUNS][NTOT][WAYS];    // solved Z / sinkhorn2 state
__device__ int   g_b2run[RUNS];
__device__ float g_S[RUNS][NTOT * NTOT];    // Gram matrix staging (22.6 MB)

__device__ __forceinline__ float wred(float v) {
  #pragma unroll
  for (int o = 16; o; o >>= 1) v += __shfl_down_sync(0xffffffffu, v, o);
  return v;
}
__device__ __forceinline__ float wsum_x(float v) {
  #pragma unroll
  for (int o = 16; o; o >>= 1) v += __shfl_xor_sync(0xffffffffu, v, o);
  return v;
}
__device__ __forceinline__ float wmax_x(float v) {
  #pragma unroll
  for (int o = 16; o; o >>= 1) v = fmaxf(v, __shfl_xor_sync(0xffffffffu, v, o));
  return v;
}
__device__ __forceinline__ float fdiv(float a, float b) { return __fdividef(a, b); }

// ---- single-warp register sinkhorn: pass-1 (count bodies to own converge) --
template<int NR, int NROWS, bool LAB>
__device__ __forceinline__ int sink_pass1(float (&P)[NR][WAYS], float ctot,
                                          int lane, int cls) {
  float u[NR];
  #pragma unroll
  for (int s = 0; s < NR; s++) u[s] = 0.f;
  int b = 0;
  for (;;) {
    float rs[NR];
    float d = 0.f;
    #pragma unroll
    for (int s = 0; s < NR; s++) {
      rs[s] = P[s][0] + P[s][1] + P[s][2] + P[s][3] + P[s][4];
      if (lane + 32 * s < NROWS) d = fmaxf(d, fabsf(u[s] - rs[s]));
    }
    float delta = wmax_x(d);
    float t[NR][WAYS];
    float cp[WAYS] = {0.f, 0.f, 0.f, 0.f, 0.f};
    #pragma unroll
    for (int s = 0; s < NR; s++) {
      float inv = (lane + 32 * s < NROWS) ? fdiv(1.0f, rs[s]) : 0.f;
      #pragma unroll
      for (int k = 0; k < WAYS; k++) { t[s][k] = P[s][k] * inv; cp[k] += t[s][k]; }
    }
    float f[WAYS];
    #pragma unroll
    for (int k = 0; k < WAYS; k++) f[k] = fdiv(ctot, wsum_x(cp[k]));
    #pragma unroll
    for (int s = 0; s < NR; s++)
      #pragma unroll
      for (int k = 0; k < WAYS; k++) t[s][k] *= f[k];
    if (LAB && lane < NSUP) {
      #pragma unroll
      for (int k = 0; k < WAYS; k++) t[0][k] = (k == cls) ? 1.f : 0.f;
    }
    if (!(delta > EPSV && b < MAXIT)) break;
    #pragma unroll
    for (int s = 0; s < NR; s++) {
      u[s] = rs[s];
      #pragma unroll
      for (int k = 0; k < WAYS; k++) P[s][k] = t[s][k];
    }
    b++;
  }
  return b;
}

// ---- single-warp register sinkhorn: replay exactly `iters` bodies ----------
template<int NR, int NROWS, bool LAB>
__device__ __forceinline__ void sink_replay(float (&P)[NR][WAYS], float ctot,
                                            int lane, int cls, int iters) {
  for (int it = 0; it < iters; it++) {
    float cp[WAYS] = {0.f, 0.f, 0.f, 0.f, 0.f};
    #pragma unroll
    for (int s = 0; s < NR; s++) {
      float rs = P[s][0] + P[s][1] + P[s][2] + P[s][3] + P[s][4];
      float inv = (lane + 32 * s < NROWS) ? fdiv(1.0f, rs) : 0.f;
      #pragma unroll
      for (int k = 0; k < WAYS; k++) { P[s][k] *= inv; cp[k] += P[s][k]; }
    }
    float f[WAYS];
    #pragma unroll
    for (int k = 0; k < WAYS; k++) f[k] = fdiv(ctot, wsum_x(cp[k]));
    #pragma unroll
    for (int s = 0; s < NR; s++)
      #pragma unroll
      for (int k = 0; k < WAYS; k++) P[s][k] *= f[k];
    if (LAB && lane < NSUP) {
      #pragma unroll
      for (int k = 0; k < WAYS; k++) P[0][k] = (k == cls) ? 1.f : 0.f;
    }
  }
}

// ---------------- KA: epoch-0 proto, Pq0, sinkhorn1 pass-1 ------------------
__global__ __launch_bounds__(160) void ka_kernel(const float* __restrict__ xs,
                                                 const float* __restrict__ xq) {
  __shared__ float ps[WAYS][DIM];
  __shared__ float pn[WAYS];
  __shared__ float Psh[NQ][WAYS];
  int run = blockIdx.x;
  int tid = threadIdx.x, w = tid >> 5, lane = tid & 31;
  const float* xsr = xs + (size_t)run * NSUP * DIM;
  const float* xqr = xq + (size_t)run * NQ * DIM;

  for (int idx = tid; idx < WAYS * DIM; idx += 160) {
    int k = idx / DIM, d = idx % DIM;
    float s = 0.f;
    #pragma unroll
    for (int sh = 0; sh < SHOT; sh++) s += xsr[(k * SHOT + sh) * DIM + d];
    float v = s / 5.0f;
    ps[k][d] = v;
    g_proto[run][k][d] = v;
  }
  __syncthreads();

  { // proto norms (warp w does class w)
    float a = 0.f;
    for (int d = lane; d < DIM; d += 32) { float v = ps[w][d]; a += v * v; }
    a = wred(a);
    if (lane == 0) pn[w] = a;
  }
  __syncthreads();

  // Pq = exp(-LAM * d2(query, proto))
  for (int q = w; q < NQ; q += 5) {
    float a0=0,a1=0,a2=0,a3=0,a4=0,an=0;
    const float* xr = xqr + q * DIM;
    #pragma unroll 4
    for (int d = lane; d < DIM; d += 32) {
      float x = xr[d];
      an += x*x;
      a0 += x*ps[0][d]; a1 += x*ps[1][d]; a2 += x*ps[2][d];
      a3 += x*ps[3][d]; a4 += x*ps[4][d];
    }
    an = wred(an); a0 = wred(a0); a1 = wred(a1); a2 = wred(a2); a3 = wred(a3); a4 = wred(a4);
    if (lane == 0) {
      float acc[5] = {a0,a1,a2,a3,a4};
      #pragma unroll
      for (int k = 0; k < WAYS; k++) {
        float d2 = fmaxf(an + pn[k] - 2.0f * acc[k], 0.0f);
        Psh[q][k] = expf(-LAM * d2);
      }
    }
  }
  __syncthreads();

  if (tid < 32) {
    float P[3][WAYS];
    #pragma unroll
    for (int s = 0; s < 3; s++) {
      int row = lane + 32 * s;
      #pragma unroll
      for (int k = 0; k < WAYS; k++) P[s][k] = (row < NQ) ? Psh[row][k] : 0.f;
    }
    int b = sink_pass1<3, NQ, false>(P, 15.0f, lane, 0);
    #pragma unroll
    for (int s = 0; s < 3; s++) {
      int row = lane + 32 * s;
      if (row < NQ)
        #pragma unroll
        for (int k = 0; k < WAYS; k++) g_P1[run][row][k] = P[s][k];
    }
    if (lane == 0) g_b1A[run] = b;
  }
}

// ---- KB (fused): replay sinkhorn1(e), entropy, blend; then either
//      Pq+pass-1 for epoch e+1 (e<2) or the epoch-2 tail (Fp/Zext). ---------
__global__ __launch_bounds__(160) void kb_kernel(const float* __restrict__ xs,
                                                 const float* __restrict__ xq,
                                                 const int* __restrict__ ys,
                                                 int epoch) {
  __shared__ float Psh[NQ][WAYS];
  __shared__ float Z[NF][WAYS];
  __shared__ float ent[NF];
  __shared__ float cs[WAYS];
  __shared__ float psh[WAYS][DIM];
  __shared__ float pn2[WAYS];
  __shared__ float dp[WAYS][WAYS];
  __shared__ float score[WAYS], maskv[WAYS];
  __shared__ float omega_s;
  int run = blockIdx.x, tid = threadIdx.x;
  int w = tid >> 5, lane = tid & 31;
  const int* ysr = ys + run * NSUP;
  const float* xsr = xs + (size_t)run * NSUP * DIM;
  const float* xqr = xq + (size_t)run * NQ * DIM;

  const int* rbuf = (epoch == 1) ? g_b1B : g_b1A;   // pass-1 counts for epoch e
  int* wbuf = (epoch == 0) ? g_b1B : g_b1A;          // counts for epoch e+1

  if (tid < 32) {  // warp 0: replay to global B, registers only
    float P[3][WAYS];
    #pragma unroll
    for (int s = 0; s < 3; s++) {
      int row = lane + 32 * s;
      #pragma unroll
      for (int k = 0; k < WAYS; k++) P[s][k] = (row < NQ) ? g_P1[run][row][k] : 0.f;
    }
    int m = 0;
    for (int i = lane; i < RUNS; i += 32) m = max(m, rbuf[i]);
    m = __reduce_max_sync(0xffffffffu, m);
    int extra = m - rbuf[run];
    sink_replay<3, NQ, false>(P, 15.0f, lane, 0, extra);
    #pragma unroll
    for (int s = 0; s < 3; s++) {
      int row = lane + 32 * s;
      if (row < NQ)
        #pragma unroll
        for (int k = 0; k < WAYS; k++) Psh[row][k] = P[s][k];
    }
  } else {
    // warps 1-4: prefetch the feature block to L2 while warp 0 replays
    int t4 = (w - 1) * 32 + lane;   // 0..127
    for (int off = t4 * 32; off < NSUP * DIM; off += 128 * 32)
      asm volatile("prefetch.global.L2 [%0];" :: "l"(xsr + off));
    for (int off = t4 * 32; off < NQ * DIM; off += 128 * 32)
      asm volatile("prefetch.global.L2 [%0];" :: "l"(xqr + off));
  }
  __syncthreads();

  // Z = [onehot(ys); Pq]
  for (int idx = tid; idx < NF * WAYS; idx += 160) {
    int i = idx / WAYS, k = idx % WAYS;
    float v = (i < NSUP) ? ((ysr[i] == k) ? 1.0f : 0.0f) : Psh[i - NSUP][k];
    Z[i][k] = v;
  }
  __syncthreads();

  // entropy per row
  if (tid < NF) {
    float p[WAYS], s = 0.f;
    #pragma unroll
    for (int k = 0; k < WAYS; k++) { p[k] = Z[tid][k] + 1e-12f; s += p[k]; }
    float H = 0.f;
    #pragma unroll
    for (int k = 0; k < WAYS; k++) { float q = p[k] / s; H -= q * logf(q); }
    ent[tid] = H / logf(5.0f);
  }
  __syncthreads();

  // Z *= (1 - ent)
  for (int idx = tid; idx < NF * WAYS; idx += 160) {
    int i = idx / WAYS;
    ((float*)Z)[idx] *= (1.0f - ent[i]);
  }
  __syncthreads();
  { // column sums via warp reductions (warp w -> class w)
    float part = 0.f;
    for (int i = lane; i < NF; i += 32) part += Z[i][w];
    part = wred(part);
    if (lane == 0) cs[w] = part;
  }
  __syncthreads();

  // new_proto + blend: row-outer loop, 4 independent column streams (MLP)
  {
    float a[4][WAYS];
    #pragma unroll
    for (int d = 0; d < 4; d++)
      #pragma unroll
      for (int k = 0; k < WAYS; k++) a[d][k] = 0.f;
    #pragma unroll 2
    for (int i = 0; i < NF; i++) {
      const float* fr = (i < NSUP) ? (xsr + i * DIM)
                                   : (xqr + (size_t)(i - NSUP) * DIM);
      float f0 = fr[tid], f1 = fr[tid + 160], f2 = fr[tid + 320], f3 = fr[tid + 480];
      #pragma unroll
      for (int k = 0; k < WAYS; k++) {
        float z = Z[i][k];
        a[0][k] += z * f0; a[1][k] += z * f1; a[2][k] += z * f2; a[3][k] += z * f3;
      }
    }
    #pragma unroll
    for (int d = 0; d < 4; d++) {
      int dcol = tid + d * 160;
      #pragma unroll
      for (int k = 0; k < WAYS; k++) {
        float np = a[d][k] / cs[k];
        float pr = 0.4f * g_proto[run][k][dcol] + 0.6f * np;
        g_proto[run][k][dcol] = pr;
        psh[k][dcol] = pr;
      }
    }
  }
  __syncthreads();

  { // new proto norms (warp w -> class w); needed by both branches
    float a = 0.f;
    for (int d = lane; d < DIM; d += 32) { float v = psh[w][d]; a += v * v; }
    a = wred(a);
    if (lane == 0) pn2[w] = a;
  }
  __syncthreads();

  if (epoch < 2) {
    // ---- fused "ka" for epoch e+1: Pq from psh, then pass-1 ----
    for (int q = w; q < NQ; q += 5) {
      float a0=0,a1=0,a2=0,a3=0,a4=0,an=0;
      const float* xr = xqr + q * DIM;
      #pragma unroll 4
      for (int d = lane; d < DIM; d += 32) {
        float x = xr[d];
        an += x*x;
        a0 += x*psh[0][d]; a1 += x*psh[1][d]; a2 += x*psh[2][d];
        a3 += x*psh[3][d]; a4 += x*psh[4][d];
      }
      an = wred(an); a0 = wred(a0); a1 = wred(a1); a2 = wred(a2); a3 = wred(a3); a4 = wred(a4);
      if (lane == 0) {
        float acc[5] = {a0,a1,a2,a3,a4};
        #pragma unroll
        for (int k = 0; k < WAYS; k++) {
          float d2 = fmaxf(an + pn2[k] - 2.0f * acc[k], 0.0f);
          Psh[q][k] = expf(-LAM * d2);
        }
      }
    }
    __syncthreads();
    if (tid < 32) {
      float P[3][WAYS];
      #pragma unroll
      for (int s = 0; s < 3; s++) {
        int row = lane + 32 * s;
        #pragma unroll
        for (int k = 0; k < WAYS; k++) P[s][k] = (row < NQ) ? Psh[row][k] : 0.f;
      }
      int b = sink_pass1<3, NQ, false>(P, 15.0f, lane, 0);
      #pragma unroll
      for (int s = 0; s < 3; s++) {
        int row = lane + 32 * s;
        if (row < NQ)
          #pragma unroll
          for (int k = 0; k < WAYS; k++) g_P1[run][row][k] = P[s][k];
      }
      if (lane == 0) wbuf[run] = b;
    }
  } else {
    // ---- epoch-2 tail: proto distance graph, mask, Fp/Zext ----
    for (int p = w; p < WAYS * WAYS; p += 5) {
      int ia = p / WAYS, ib = p % WAYS;
      float acc = 0.f;
      for (int d = lane; d < DIM; d += 32) acc += psh[ia][d] * psh[ib][d];
      acc = wred(acc);
      if (lane == 0) {
        float d2 = fmaxf(pn2[ia] + pn2[ib] - 2.0f * acc, 0.0f);
        dp[ia][ib] = expf(-LAM * d2);
      }
    }
    __syncthreads();
    if (tid < WAYS) {
      float p[WAYS], s = 0.f;
      #pragma unroll
      for (int k = 0; k < WAYS; k++) { p[k] = dp[tid][k] + 1e-12f; s += p[k]; }
      float H = 0.f;
      #pragma unroll
      for (int k = 0; k < WAYS; k++) { float q = p[k] / s; H -= q * logf(q); }
      score[tid] = H / logf(5.0f);
    }
    if (w == 0) { // omega = mean(ent)
      float part = 0.f;
      for (int i = lane; i < NF; i += 32) part += ent[i];
      part = wred(part);
      if (lane == 0) omega_s = part / 100.0f;
    }
    __syncthreads();
    if (tid < WAYS) maskv[tid] = (score[tid] < omega_s) ? 1.0f : 0.0f;
    __syncthreads();
    for (int idx = tid; idx < WAYS * DIM; idx += 160) {
      int k = idx / DIM, d = idx % DIM;
      g_Fp[run][k][d] = psh[k][d] * maskv[k];
    }
    for (int idx = tid; idx < NF * WAYS; idx += 160) {
      int i = idx / WAYS, k = idx % WAYS;
      g_Zext[run][i][k] = Z[i][k];
    }
    if (tid < WAYS * WAYS) {
      int ia = tid / WAYS, k = tid % WAYS;
      g_Zext[run][NF + ia][k] = dp[ia][k] * maskv[ia];
    }
  }
}

// ---------------- KCG: f32x2 triangular Gram -> g_S -------------------------
#define FROWS 112
#define KCHUNK 64
#define FPAD 66                      // even: 8B-aligned LDS.64 pairs
#define NT6 18                       // ceil(105/6) tile rows (6x6 tiles)
#define NTRI (NT6 * (NT6 + 1) / 2)   // 171 triangular tiles
#define KCG_SMEM (FROWS * FPAD * 4)  // 29,568B

__global__ __launch_bounds__(256) void kcg_kernel(const float* __restrict__ xs,
                                                  const float* __restrict__ xq) {
  extern __shared__ float sm[];
  float* Fsh = sm;
  int run = blockIdx.x, tid = threadIdx.x;
  const float* xsr = xs + (size_t)run * NSUP * DIM;
  const float* xqr = xq + (size_t)run * NQ * DIM;

  // triangular 6x6 tile mapping: threads 0..170 own tiles tix>=tjx
  bool act = tid < NTRI;
  int tix = 0, tjx = 0;
  if (act) {
    tix = (int)((sqrtf(8.0f * (float)tid + 1.0f) - 1.0f) * 0.5f);
    while ((tix + 1) * (tix + 2) / 2 <= tid) tix++;
    while (tix * (tix + 1) / 2 > tid) tix--;
    tjx = tid - tix * (tix + 1) / 2;
  }

  unsigned long long acc2[6][6];
  #pragma unroll
  for (int r = 0; r < 6; r++)
    #pragma unroll
    for (int c = 0; c < 6; c++) acc2[r][c] = 0ull;

  for (int c0 = 0; c0 < DIM; c0 += KCHUNK) {
    __syncthreads();
    for (int e = tid; e < FROWS * KCHUNK; e += 256) {
      int r = e >> 6, dd = e & 63;
      float v = 0.f;
      if (r < NSUP)       v = xsr[r * DIM + c0 + dd];
      else if (r < NF)    v = xqr[(r - NSUP) * DIM + c0 + dd];
      else if (r < NTOT)  v = g_Fp[run][r - NF][c0 + dd];
      Fsh[r * FPAD + dd] = v;
    }
    __syncthreads();
    if (act) {
      #pragma unroll 4
      for (int dd = 0; dd < KCHUNK; dd += 2) {
        unsigned long long a2[6], b2[6];
        #pragma unroll
        for (int r = 0; r < 6; r++)
          a2[r] = *(const unsigned long long*)&Fsh[(tix * 6 + r) * FPAD + dd];
        #pragma unroll
        for (int c = 0; c < 6; c++)
          b2[c] = *(const unsigned long long*)&Fsh[(tjx * 6 + c) * FPAD + dd];
        #pragma unroll
        for (int r = 0; r < 6; r++)
          #pragma unroll
          for (int c = 0; c < 6; c++)
            asm("fma.rn.f32x2 %0, %1, %2, %0;"
                : "+l"(acc2[r][c]) : "l"(a2[r]), "l"(b2[c]));
      }
    }
  }

  // write S (both halves) straight to global
  if (act) {
    float* Sr = g_S[run];
    #pragma unroll
    for (int r = 0; r < 6; r++) {
      int gi = tix * 6 + r;
      #pragma unroll
      for (int c = 0; c < 6; c++) {
        int gj = tjx * 6 + c;
        if (gi < NTOT && gj < NTOT) {
          float2 v2 = *(float2*)&acc2[r][c];
          float sv = v2.x + v2.y;
          Sr[gi * NTOT + gj] = sv;
          if (tix > tjx) Sr[gj * NTOT + gi] = sv;
        }
      }
    }
  }
}

// ---------------- KCS: graph + register Cholesky + solves -------------------
#define KCS_SMEM (NTOT * NTOT * 4)   // 44,100B

__global__ __launch_bounds__(256) void kcs_kernel() {
  extern __shared__ float sm[];
  float* As  = sm;                  // S then A workspace
  float* Lsh = sm;                  // L after Cholesky (aliased)
  __shared__ float n2[FROWS];
  __shared__ float rsum[FROWS];
  __shared__ float Dm[FROWS];
  __shared__ float colbuf[2][FROWS];
  __shared__ float sh_piv;
  __shared__ float yv[NTOT][WAYS];

  int run = blockIdx.x, tid = threadIdx.x;
  int ti = tid >> 4, tj = tid & 15;      // 7x7 grid mapping
  int w = tid >> 5, lane = tid & 31;

  // ---- load S coalesced ----
  for (int idx = tid; idx < NTOT * NTOT; idx += 256)
    As[idx] = g_S[run][idx];
  __syncthreads();

  // ---- diag norms ----
  if (tid < FROWS) {
    n2[tid] = (tid < NTOT) ? As[tid * NTOT + tid] : 0.f;
    rsum[tid] = 0.f;
  }
  __syncthreads();

  // ---- 7x7 tiles: W = exp(-LAM*d2), rowsums ----
  float acc[7][7];
  #pragma unroll
  for (int r = 0; r < 7; r++) {
    int gi = ti * 7 + r;
    #pragma unroll
    for (int c = 0; c < 7; c++) {
      int gj = tj * 7 + c;
      float wv = 0.f;
      if (gi < NTOT && gj < NTOT && gi != gj) {
        float d2 = fmaxf(n2[gi] + n2[gj] - 2.0f * As[gi * NTOT + gj], 0.0f);
        wv = expf(-LAM * d2);
      }
      acc[r][c] = wv;
    }
  }
  #pragma unroll
  for (int r = 0; r < 7; r++) {
    int gi = ti * 7 + r;
    float p = 0.f;
    #pragma unroll
    for (int c = 0; c < 7; c++) p += acc[r][c];
    if (gi < NTOT) atomicAdd(&rsum[gi], p);
  }
  __syncthreads();
  if (tid < FROWS) Dm[tid] = (tid < NTOT) ? (1.0f / sqrtf(rsum[tid])) : 0.f;
  __syncthreads();

  // ---- A = I - ALPHA * Dm_i W Dm_j (in registers) ----
  #pragma unroll
  for (int r = 0; r < 7; r++) {
    int gi = ti * 7 + r;
    float di = Dm[gi];
    #pragma unroll
    for (int c = 0; c < 7; c++) {
      int gj = tj * 7 + c;
      acc[r][c] = ((gi == gj) ? 1.0f : 0.0f) - ALPHA_ * di * acc[r][c] * Dm[gj];
    }
  }
  __syncthreads();

  // ---- register-resident Cholesky, rank-1 updates via shared column bcast --
  for (int jt = 0; jt < 15; jt++) {
    #pragma unroll
    for (int jc = 0; jc < 7; jc++) {
      int j = jt * 7 + jc;
      int buf = j & 1;
      if (tid < FROWS) colbuf[buf][tid] = 0.f;
      if (ti == jt && tj == jt) {
        float pv = sqrtf(acc[jc][jc]);
        acc[jc][jc] = pv;
        sh_piv = pv;
      }
      __syncthreads();
      if (tj == jt) {
        float ip = 1.0f / sh_piv;
        #pragma unroll
        for (int r = 0; r < 7; r++) {
          int gi = ti * 7 + r;
          if (gi > j) { acc[r][jc] *= ip; colbuf[buf][gi] = acc[r][jc]; }
        }
      }
      __syncthreads();
      float rv[7], cv[7];
      #pragma unroll
      for (int r = 0; r < 7; r++) rv[r] = colbuf[buf][ti * 7 + r];
      #pragma unroll
      for (int c = 0; c < 7; c++) cv[c] = colbuf[buf][tj * 7 + c];
      #pragma unroll
      for (int r = 0; r < 7; r++)
        #pragma unroll
        for (int c = 0; c < 7; c++) acc[r][c] -= rv[r] * cv[c];
    }
  }
  __syncthreads();   // As region dead; reuse as Lsh

  // ---- dump L (lower + diag) to shared ----
  #pragma unroll
  for (int r = 0; r < 7; r++) {
    int gi = ti * 7 + r;
    #pragma unroll
    for (int c = 0; c < 7; c++) {
      int gj = tj * 7 + c;
      if (gi < NTOT && gj < NTOT && gj <= gi) Lsh[gi * NTOT + gj] = acc[r][c];
    }
  }
  for (int idx = tid; idx < NTOT * WAYS; idx += 256)
    ((float*)yv)[idx] = ((const float*)g_Zext[run])[idx];
  __syncthreads();

  // ---- triangular solves: warp w owns RHS col w; shfl-broadcast sweep ----
  if (w < WAYS) {
    float rr[4], dinv[4];
    #pragma unroll
    for (int s = 0; s < 4; s++) {
      int row = lane + 32 * s;
      rr[s]   = (row < NTOT) ? yv[row][w] : 0.f;
      dinv[s] = (row < NTOT) ? (1.0f / Lsh[row * NTOT + row]) : 0.f;
    }
    // forward: L y = b
    for (int i = 0; i < NTOT; i++) {
      int s_i = i >> 5, src = i & 31;
      float yi = rr[s_i] * dinv[s_i];
      yi = __shfl_sync(0xffffffffu, yi, src);
      if (lane == src) rr[s_i] = yi;
      #pragma unroll
      for (int s = 0; s < 4; s++) {
        int row = lane + 32 * s;
        if (row > i && row < NTOT) rr[s] -= Lsh[row * NTOT + i] * yi;
      }
    }
    // backward: L^T x = y
    for (int i = NTOT - 1; i >= 0; i--) {
      int s_i = i >> 5, src = i & 31;
      float xi = rr[s_i] * dinv[s_i];
      xi = __shfl_sync(0xffffffffu, xi, src);
      if (lane == src) rr[s_i] = xi;
      #pragma unroll
      for (int s = 0; s < 4; s++) {
        int row = lane + 32 * s;
        if (row < i) rr[s] -= Lsh[i * NTOT + row] * xi;
      }
    }
    #pragma unroll
    for (int s = 0; s < 4; s++) {
      int row = lane + 32 * s;
      if (row < NTOT) yv[row][w] = rr[s];
    }
  }
  __syncthreads();

  // ---- write solved Z; sinkhorn2 runs in kc2 ----
  for (int idx = tid; idx < NTOT * WAYS; idx += 256)
    ((float*)g_Z0[run])[idx] = ((const float*)yv)[idx];
}

// ---------------- KC2: sinkhorn2 pass-1, 1 warp per run ---------------------
__global__ __launch_bounds__(128) void kc2_kernel(const int* __restrict__ ys) {
  int tid = threadIdx.x, w = tid >> 5, lane = tid & 31;
  int run = blockIdx.x * 4 + w;
  const int* ysr = ys + run * NSUP;
  float P[4][WAYS];
  #pragma unroll
  for (int s = 0; s < 4; s++) {
    int row = lane + 32 * s;
    #pragma unroll
    for (int k = 0; k < WAYS; k++) P[s][k] = (row < NTOT) ? g_Z0[run][row][k] : 0.f;
  }
  int cls = (lane < NSUP) ? ysr[lane] : 0;
  int b = sink_pass1<4, NTOT, true>(P, 21.0f, lane, cls);
  #pragma unroll
  for (int s = 0; s < 4; s++) {
    int row = lane + 32 * s;
    if (row < NTOT)
      #pragma unroll
      for (int k = 0; k < WAYS; k++) g_Z0[run][row][k] = P[s][k];
  }
  if (lane == 0) g_b2run[run] = b;
}

// ---------------- KD: 1 warp per run: replay sinkhorn2, argmax, accuracy ----
__global__ __launch_bounds__(128) void kd_kernel(const int* __restrict__ ys,
                                                 const int* __restrict__ yq,
                                                 float* __restrict__ out) {
  int tid = threadIdx.x, w = tid >> 5, lane = tid & 31;
  int run = blockIdx.x * 4 + w;
  const int* ysr = ys + run * NSUP;
  float P[4][WAYS];
  #pragma unroll
  for (int s = 0; s < 4; s++) {
    int row = lane + 32 * s;
    #pragma unroll
    for (int k = 0; k < WAYS; k++) P[s][k] = (row < NTOT) ? g_Z0[run][row][k] : 0.f;
  }
  int cls = (lane < NSUP) ? ysr[lane] : 0;
  int m = 0;
  for (int i = lane; i < RUNS; i += 32) m = max(m, g_b2run[i]);
  m = __reduce_max_sync(0xffffffffu, m);
  int extra = m - g_b2run[run];
  sink_replay<4, NTOT, true>(P, 21.0f, lane, cls, extra);

  int cnt = 0;
  #pragma unroll
  for (int s = 0; s < 4; s++) {
    int row = lane + 32 * s;
    if (row >= NSUP && row < NF) {
      float best = P[s][0]; int bi = 0;
      #pragma unroll
      for (int k = 1; k < WAYS; k++)
        if (P[s][k] > best) { best = P[s][k]; bi = k; }
      if (bi == yq[run * NQ + (row - NSUP)]) cnt++;
    }
  }
  #pragma unroll
  for (int o = 16; o; o >>= 1) cnt += __shfl_xor_sync(0xffffffffu, cnt, o);
  if (lane == 0) out[run] = (float)cnt / 75.0f;
}

// ---------------------------------------------------------------------------
extern "C" void kernel_launch(void* const* d_in, const int* in_sizes, int n_in,
                              void* d_out, int out_size) {
  const float* xs = (const float*)d_in[0];
  const float* xq = (const float*)d_in[1];
  const int*   ys = (const int*)d_in[2];
  const int*   yq = (const int*)d_in[3];
  float* out = (float*)d_out;

  cudaFuncSetAttribute(kcg_kernel, cudaFuncAttributeMaxDynamicSharedMemorySize,
                       KCG_SMEM);
  cudaFuncSetAttribute(kcs_kernel, cudaFuncAttributeMaxDynamicSharedMemorySize,
                       KCS_SMEM);

  ka_kernel<<<RUNS, 160>>>(xs, xq);
  for (int e = 0; e < 3; e++)
    kb_kernel<<<RUNS, 160>>>(xs, xq, ys, e);
  kcg_kernel<<<RUNS, 256, KCG_SMEM>>>(xs, xq);
  kcs_kernel<<<RUNS, 256, KCS_SMEM>>>();
  kc2_kernel<<<RUNS / 4, 128>>>(ys);
  kd_kernel<<<RUNS / 4, 128>>>(ys, yq, out);
}

// round 12
// speedup vs baseline: 1.9296x; 1.9296x over previous
#include <cuda_runtime.h>
#include <math.h>
#include <stdint.h>

#define RUNS 512
#define WAYS 5
#define SHOT 5
#define NSUP 25
#define NQ   75
#define NF   100
#define NTOT 105
#define DIM  640
#define LAM  10.0f
#define ALPHA_ 0.7f
#define EPSV 1e-3f
#define MAXIT 1000

#define GST 101        // shared G stride (conflict-free for stride-100 col reads)
#define ST  107        // shared S stride in kb2 (105 rows; 107%32=11 -> conflict-free)

// ---------------- device scratch (static: no allocations allowed) ----------
__device__ float g_G[RUNS][NF * NF];        // feature Gram (20.5 MB)
__device__ float g_c[RUNS][WAYS * NF];      // proto coefficients [k*100+i]
__device__ float g_P1[RUNS][NQ][WAYS];      // sinkhorn1 state after pass-1
__device__ int   g_b1A[RUNS];               // per-run body counts (double buf)
__device__ int   g_b1B[RUNS];
__device__ float g_Z0[RUNS][NTOT][WAYS];    // solved Z / sinkhorn2 state
__device__ int   g_b2run[RUNS];

__device__ __forceinline__ float wred(float v) {
  #pragma unroll
  for (int o = 16; o; o >>= 1) v += __shfl_down_sync(0xffffffffu, v, o);
  return v;
}
__device__ __forceinline__ float wsum_x(float v) {
  #pragma unroll
  for (int o = 16; o; o >>= 1) v += __shfl_xor_sync(0xffffffffu, v, o);
  return v;
}
__device__ __forceinline__ float wmax_x(float v) {
  #pragma unroll
  for (int o = 16; o; o >>= 1) v = fmaxf(v, __shfl_xor_sync(0xffffffffu, v, o));
  return v;
}
__device__ __forceinline__ float fdiv(float a, float b) { return __fdividef(a, b); }

// ---- single-warp register sinkhorn: pass-1 (count bodies to own converge) --
template<int NR, int NROWS, bool LAB>
__device__ __forceinline__ int sink_pass1(float (&P)[NR][WAYS], float ctot,
                                          int lane, int cls) {
  float u[NR];
  #pragma unroll
  for (int s = 0; s < NR; s++) u[s] = 0.f;
  int b = 0;
  for (;;) {
    float rs[NR];
    float d = 0.f;
    #pragma unroll
    for (int s = 0; s < NR; s++) {
      rs[s] = P[s][0] + P[s][1] + P[s][2] + P[s][3] + P[s][4];
      if (lane + 32 * s < NROWS) d = fmaxf(d, fabsf(u[s] - rs[s]));
    }
    float delta = wmax_x(d);
    float t[NR][WAYS];
    float cp[WAYS] = {0.f, 0.f, 0.f, 0.f, 0.f};
    #pragma unroll
    for (int s = 0; s < NR; s++) {
      float inv = (lane + 32 * s < NROWS) ? fdiv(1.0f, rs[s]) : 0.f;
      #pragma unroll
      for (int k = 0; k < WAYS; k++) { t[s][k] = P[s][k] * inv; cp[k] += t[s][k]; }
    }
    float f[WAYS];
    #pragma unroll
    for (int k = 0; k < WAYS; k++) f[k] = fdiv(ctot, wsum_x(cp[k]));
    #pragma unroll
    for (int s = 0; s < NR; s++)
      #pragma unroll
      for (int k = 0; k < WAYS; k++) t[s][k] *= f[k];
    if (LAB && lane < NSUP) {
      #pragma unroll
      for (int k = 0; k < WAYS; k++) t[0][k] = (k == cls) ? 1.f : 0.f;
    }
    if (!(delta > EPSV && b < MAXIT)) break;
    #pragma unroll
    for (int s = 0; s < NR; s++) {
      u[s] = rs[s];
      #pragma unroll
      for (int k = 0; k < WAYS; k++) P[s][k] = t[s][k];
    }
    b++;
  }
  return b;
}

// ---- single-warp register sinkhorn: replay exactly `iters` bodies ----------
template<int NR, int NROWS, bool LAB>
__device__ __forceinline__ void sink_replay(float (&P)[NR][WAYS], float ctot,
                                            int lane, int cls, int iters) {
  for (int it = 0; it < iters; it++) {
    float cp[WAYS] = {0.f, 0.f, 0.f, 0.f, 0.f};
    #pragma unroll
    for (int s = 0; s < NR; s++) {
      float rs = P[s][0] + P[s][1] + P[s][2] + P[s][3] + P[s][4];
      float inv = (lane + 32 * s < NROWS) ? fdiv(1.0f, rs) : 0.f;
      #pragma unroll
      for (int k = 0; k < WAYS; k++) { P[s][k] *= inv; cp[k] += P[s][k]; }
    }
    float f[WAYS];
    #pragma unroll
    for (int k = 0; k < WAYS; k++) f[k] = fdiv(ctot, wsum_x(cp[k]));
    #pragma unroll
    for (int s = 0; s < NR; s++)
      #pragma unroll
      for (int k = 0; k < WAYS; k++) P[s][k] *= f[k];
    if (LAB && lane < NSUP) {
      #pragma unroll
      for (int k = 0; k < WAYS; k++) P[0][k] = (k == cls) ? 1.f : 0.f;
    }
  }
}

// ---------------- KGRAM: f32x2 triangular 100x100 feature Gram -> g_G -------
#define GNT 17                        // ceil(100/6) tile rows
#define GNTRI (GNT * (GNT + 1) / 2)   // 153 triangular tiles
#define GFR 102
#define GFPAD 66
#define KG_SMEM (NF * GST * 4)        // 40,400B (>= GFR*GFPAD*4 = 26,928B)

__global__ __launch_bounds__(256, 2) void kgram_kernel(const float* __restrict__ xs,
                                                       const float* __restrict__ xq) {
  extern __shared__ float sm[];
  float* Fsh = sm;                    // during Gram
  float* Gsh = sm;                    // after (stride GST)
  int run = blockIdx.x, tid = threadIdx.x;
  const float* xsr = xs + (size_t)run * NSUP * DIM;
  const float* xqr = xq + (size_t)run * NQ * DIM;

  bool act = tid < GNTRI;
  int tix = 0, tjx = 0;
  if (act) {
    tix = (int)((sqrtf(8.0f * (float)tid + 1.0f) - 1.0f) * 0.5f);
    while ((tix + 1) * (tix + 2) / 2 <= tid) tix++;
    while (tix * (tix + 1) / 2 > tid) tix--;
    tjx = tid - tix * (tix + 1) / 2;
  }

  unsigned long long acc2[6][6];
  #pragma unroll
  for (int r = 0; r < 6; r++)
    #pragma unroll
    for (int c = 0; c < 6; c++) acc2[r][c] = 0ull;

  for (int c0 = 0; c0 < DIM; c0 += 64) {
    __syncthreads();
    for (int e = tid; e < GFR * 64; e += 256) {
      int r = e >> 6, dd = e & 63;
      float v = 0.f;
      if (r < NSUP)    v = xsr[r * DIM + c0 + dd];
      else if (r < NF) v = xqr[(r - NSUP) * DIM + c0 + dd];
      Fsh[r * GFPAD + dd] = v;
    }
    __syncthreads();
    if (act) {
      #pragma unroll 4
      for (int dd = 0; dd < 64; dd += 2) {
        unsigned long long a2[6], b2[6];
        #pragma unroll
        for (int r = 0; r < 6; r++)
          a2[r] = *(const unsigned long long*)&Fsh[(tix * 6 + r) * GFPAD + dd];
        #pragma unroll
        for (int c = 0; c < 6; c++)
          b2[c] = *(const unsigned long long*)&Fsh[(tjx * 6 + c) * GFPAD + dd];
        #pragma unroll
        for (int r = 0; r < 6; r++)
          #pragma unroll
          for (int c = 0; c < 6; c++)
            asm("fma.rn.f32x2 %0, %1, %2, %0;"
                : "+l"(acc2[r][c]) : "l"(a2[r]), "l"(b2[c]));
      }
    }
  }
  __syncthreads();   // Fsh dead; reuse as Gsh

  if (act) {
    #pragma unroll
    for (int r = 0; r < 6; r++) {
      int gi = tix * 6 + r;
      #pragma unroll
      for (int c = 0; c < 6; c++) {
        int gj = tjx * 6 + c;
        if (gi < NF && gj < NF) {
          float2 v2 = *(float2*)&acc2[r][c];
          float sv = v2.x + v2.y;
          Gsh[gi * GST + gj] = sv;
          if (tix > tjx) Gsh[gj * GST + gi] = sv;
        }
      }
    }
  }
  __syncthreads();
  // coalesced store
  for (int idx = tid; idx < NF * NF; idx += 256) {
    int i = idx / NF, j = idx % NF;
    g_G[run][idx] = Gsh[i * GST + j];
  }
}

// ---------------- KEA: epoch-0 Pq from G, sinkhorn1 pass-1 ------------------
__global__ __launch_bounds__(160) void kea_kernel(const int* __restrict__ ys) {
  extern __shared__ float sm[];
  float* Gs = sm;                     // [100][GST]
  __shared__ float tsh[WAYS * NF];
  __shared__ float pn2[WAYS];
  __shared__ float Psh[NQ][WAYS];
  __shared__ int ysh[NSUP];
  int run = blockIdx.x, tid = threadIdx.x;
  int w = tid >> 5, lane = tid & 31;
  const int* ysr = ys + run * NSUP;

  for (int idx = tid; idx < NF * NF; idx += 160) {
    int i = idx / NF, j = idx % NF;
    Gs[i * GST + j] = g_G[run][idx];
  }
  if (tid < NSUP) ysh[tid] = ysr[tid];
  __syncthreads();

  // write c0 to g_c
  for (int idx = tid; idx < WAYS * NF; idx += 160) {
    int k = idx / NF, i = idx % NF;
    g_c[run][idx] = (i < NSUP && ysh[i] == k) ? 0.2f : 0.f;
  }

  // t_k[i] = 0.2 * sum_{i' in class k} G[i][i']
  if (tid < NF) {
    float gv[NSUP];
    #pragma unroll
    for (int i2 = 0; i2 < NSUP; i2++) gv[i2] = Gs[tid * GST + i2];
    #pragma unroll
    for (int k = 0; k < WAYS; k++) {
      float s = 0.f;
      #pragma unroll
      for (int i2 = 0; i2 < NSUP; i2++) s += (ysh[i2] == k) ? gv[i2] : 0.f;
      tsh[k * NF + tid] = 0.2f * s;
    }
  }
  __syncthreads();

  // pn[k] = 0.2 * sum_{i in class k} t_k[i]   (warp w -> class w)
  {
    float v = (lane < NSUP && ysh[lane] == w) ? tsh[w * NF + lane] : 0.f;
    v = wred(v);
    if (lane == 0) pn2[w] = 0.2f * v;
  }
  __syncthreads();

  if (tid < NQ) {
    int row = NSUP + tid;
    float nq2 = Gs[row * GST + row];
    #pragma unroll
    for (int k = 0; k < WAYS; k++) {
      float d2 = fmaxf(nq2 + pn2[k] - 2.0f * tsh[k * NF + row], 0.0f);
      Psh[tid][k] = expf(-LAM * d2);
    }
  }
  __syncthreads();

  if (tid < 32) {
    float P[3][WAYS];
    #pragma unroll
    for (int s = 0; s < 3; s++) {
      int row = lane + 32 * s;
      #pragma unroll
      for (int k = 0; k < WAYS; k++) P[s][k] = (row < NQ) ? Psh[row][k] : 0.f;
    }
    int b = sink_pass1<3, NQ, false>(P, 15.0f, lane, 0);
    #pragma unroll
    for (int s = 0; s < 3; s++) {
      int row = lane + 32 * s;
      if (row < NQ)
        #pragma unroll
        for (int k = 0; k < WAYS; k++) g_P1[run][row][k] = P[s][k];
    }
    if (lane == 0) g_b1A[run] = b;
  }
}

// ---------------- KB01 (e=0,1): replay, blend coeffs, Pq(e+1), pass-1 -------
__global__ __launch_bounds__(160) void kb01_kernel(const int* __restrict__ ys,
                                                   int epoch) {
  extern __shared__ float sm[];
  float* Gs = sm;                     // [100][GST]
  __shared__ float csh[WAYS * NF];
  __shared__ float tsh[WAYS * NF];
  __shared__ float Psh[NQ][WAYS];
  __shared__ float Z[NF][WAYS];
  __shared__ float ent[NF];
  __shared__ float cs[WAYS];
  __shared__ float pn2[WAYS];
  __shared__ int ysh[NSUP];
  int run = blockIdx.x, tid = threadIdx.x;
  int w = tid >> 5, lane = tid & 31;
  const int* ysr = ys + run * NSUP;

  const int* rbuf = (epoch == 1) ? g_b1B : g_b1A;
  int* wbuf = (epoch == 0) ? g_b1B : g_b1A;

  if (tid < 32) {  // warp 0: replay to global max
    float P[3][WAYS];
    #pragma unroll
    for (int s = 0; s < 3; s++) {
      int row = lane + 32 * s;
      #pragma unroll
      for (int k = 0; k < WAYS; k++) P[s][k] = (row < NQ) ? g_P1[run][row][k] : 0.f;
    }
    int m = 0;
    for (int i = lane; i < RUNS; i += 32) m = max(m, rbuf[i]);
    m = __reduce_max_sync(0xffffffffu, m);
    sink_replay<3, NQ, false>(P, 15.0f, lane, 0, m - rbuf[run]);
    #pragma unroll
    for (int s = 0; s < 3; s++) {
      int row = lane + 32 * s;
      if (row < NQ)
        #pragma unroll
        for (int k = 0; k < WAYS; k++) Psh[row][k] = P[s][k];
    }
  } else {
    int t4 = tid - 32;   // 0..127: load G + c + ys
    for (int idx = t4; idx < NF * NF; idx += 128) {
      int i = idx / NF, j = idx % NF;
      Gs[i * GST + j] = g_G[run][idx];
    }
    for (int idx = t4; idx < WAYS * NF; idx += 128) csh[idx] = g_c[run][idx];
    if (t4 < NSUP) ysh[t4] = ysr[t4];
  }
  __syncthreads();

  // Z = [onehot; Pq]
  for (int idx = tid; idx < NF * WAYS; idx += 160) {
    int i = idx / WAYS, k = idx % WAYS;
    Z[i][k] = (i < NSUP) ? ((ysh[i] == k) ? 1.0f : 0.0f) : Psh[i - NSUP][k];
  }
  __syncthreads();
  if (tid < NF) {
    float p[WAYS], s = 0.f;
    #pragma unroll
    for (int k = 0; k < WAYS; k++) { p[k] = Z[tid][k] + 1e-12f; s += p[k]; }
    float H = 0.f;
    #pragma unroll
    for (int k = 0; k < WAYS; k++) { float q = p[k] / s; H -= q * logf(q); }
    ent[tid] = H / logf(5.0f);
  }
  __syncthreads();
  for (int idx = tid; idx < NF * WAYS; idx += 160)
    ((float*)Z)[idx] *= (1.0f - ent[idx / WAYS]);
  __syncthreads();
  {
    float part = 0.f;
    for (int i = lane; i < NF; i += 32) part += Z[i][w];
    part = wred(part);
    if (lane == 0) cs[w] = part;
  }
  __syncthreads();

  // c_new = 0.4 c + 0.6 Z/cs  (in place)
  for (int idx = tid; idx < WAYS * NF; idx += 160) {
    int k = idx / NF, i = idx % NF;
    float v = 0.4f * csh[idx] + 0.6f * Z[i][k] / cs[k];
    csh[idx] = v;
    g_c[run][idx] = v;
  }
  __syncthreads();

  // t_k = G c_k
  if (tid < NF) {
    float a[WAYS] = {0.f, 0.f, 0.f, 0.f, 0.f};
    for (int j = 0; j < NF; j++) {
      float g = Gs[tid * GST + j];
      #pragma unroll
      for (int k = 0; k < WAYS; k++) a[k] += g * csh[k * NF + j];
    }
    #pragma unroll
    for (int k = 0; k < WAYS; k++) tsh[k * NF + tid] = a[k];
  }
  __syncthreads();

  { // pn[k] = c_k . t_k  (warp w -> class w)
    float v = 0.f;
    for (int i = lane; i < NF; i += 32) v += csh[w * NF + i] * tsh[w * NF + i];
    v = wred(v);
    if (lane == 0) pn2[w] = v;
  }
  __syncthreads();

  if (tid < NQ) {
    int row = NSUP + tid;
    float nq2 = Gs[row * GST + row];
    #pragma unroll
    for (int k = 0; k < WAYS; k++) {
      float d2 = fmaxf(nq2 + pn2[k] - 2.0f * tsh[k * NF + row], 0.0f);
      Psh[tid][k] = expf(-LAM * d2);
    }
  }
  __syncthreads();

  if (tid < 32) {
    float P[3][WAYS];
    #pragma unroll
    for (int s = 0; s < 3; s++) {
      int row = lane + 32 * s;
      #pragma unroll
      for (int k = 0; k < WAYS; k++) P[s][k] = (row < NQ) ? Psh[row][k] : 0.f;
    }
    int b = sink_pass1<3, NQ, false>(P, 15.0f, lane, 0);
    #pragma unroll
    for (int s = 0; s < 3; s++) {
      int row = lane + 32 * s;
      if (row < NQ)
        #pragma unroll
        for (int k = 0; k < WAYS; k++) g_P1[run][row][k] = P[s][k];
    }
    if (lane == 0) wbuf[run] = b;
  }
}

// ---- KB2 (e=2): replay, blend, build S from G, graph, Cholesky, solves -----
#define FROWS 112
#define KB2_SMEM (NTOT * ST * 4)   // 44,940B

__global__ __launch_bounds__(256, 2) void kb2_kernel(const int* __restrict__ ys) {
  extern __shared__ float sm[];
  float* As  = sm;                  // [105][ST]: G + proto rows -> W -> (L)
  float* Lsh = sm;
  __shared__ float csh[WAYS * NF];
  __shared__ float tsh[WAYS * NF];
  __shared__ float Psh[NQ][WAYS];
  __shared__ float ent[NF];
  __shared__ float cs[WAYS];
  __shared__ float crs[WAYS][WAYS];
  __shared__ float dp[WAYS][WAYS];
  __shared__ float score[WAYS], maskv[WAYS];
  __shared__ float omega_s;
  __shared__ int ysh[NSUP];
  __shared__ float n2[FROWS];
  __shared__ float rsum[FROWS];
  __shared__ float Dm[FROWS];
  __shared__ float colbuf[2][FROWS];
  __shared__ float sh_piv;
  __shared__ float yv[NTOT][WAYS];

  int run = blockIdx.x, tid = threadIdx.x;
  int ti = tid >> 4, tj = tid & 15;
  int w = tid >> 5, lane = tid & 31;
  const int* ysr = ys + run * NSUP;

  if (tid < 32) {  // warp 0: replay sinkhorn1 (epoch 2 counts in g_b1A)
    float P[3][WAYS];
    #pragma unroll
    for (int s = 0; s < 3; s++) {
      int row = lane + 32 * s;
      #pragma unroll
      for (int k = 0; k < WAYS; k++) P[s][k] = (row < NQ) ? g_P1[run][row][k] : 0.f;
    }
    int m = 0;
    for (int i = lane; i < RUNS; i += 32) m = max(m, g_b1A[i]);
    m = __reduce_max_sync(0xffffffffu, m);
    sink_replay<3, NQ, false>(P, 15.0f, lane, 0, m - g_b1A[run]);
    #pragma unroll
    for (int s = 0; s < 3; s++) {
      int row = lane + 32 * s;
      if (row < NQ)
        #pragma unroll
        for (int k = 0; k < WAYS; k++) Psh[row][k] = P[s][k];
    }
  } else {
    int t7 = tid - 32;   // 0..223
    for (int idx = t7; idx < NF * NF; idx += 224) {
      int i = idx / NF, j = idx % NF;
      As[i * ST + j] = g_G[run][idx];
    }
    for (int idx = t7; idx < WAYS * NF; idx += 224) csh[idx] = g_c[run][idx];
    if (t7 < NSUP) ysh[t7] = ysr[t7];
  }
  __syncthreads();

  // Z (into yv rows 0..99), entropy, weight, cs
  for (int idx = tid; idx < NF * WAYS; idx += 256) {
    int i = idx / WAYS, k = idx % WAYS;
    yv[i][k] = (i < NSUP) ? ((ysh[i] == k) ? 1.0f : 0.0f) : Psh[i - NSUP][k];
  }
  __syncthreads();
  if (tid < NF) {
    float p[WAYS], s = 0.f;
    #pragma unroll
    for (int k = 0; k < WAYS; k++) { p[k] = yv[tid][k] + 1e-12f; s += p[k]; }
    float H = 0.f;
    #pragma unroll
    for (int k = 0; k < WAYS; k++) { float q = p[k] / s; H -= q * logf(q); }
    ent[tid] = H / logf(5.0f);
  }
  __syncthreads();
  for (int idx = tid; idx < NF * WAYS; idx += 256)
    ((float*)yv)[idx] *= (1.0f - ent[idx / WAYS]);
  __syncthreads();
  if (w < WAYS) {
    float part = 0.f;
    for (int i = lane; i < NF; i += 32) part += yv[i][w];
    part = wred(part);
    if (lane == 0) cs[w] = part;
  }
  __syncthreads();

  // c_new (in place; no global write needed in final epoch)
  for (int idx = tid; idx < WAYS * NF; idx += 256) {
    int k = idx / NF, i = idx % NF;
    csh[idx] = 0.4f * csh[idx] + 0.6f * yv[i][k] / cs[k];
  }
  __syncthreads();

  // t_k = G c_k (G part of As)
  if (tid < NF) {
    float a[WAYS] = {0.f, 0.f, 0.f, 0.f, 0.f};
    for (int j = 0; j < NF; j++) {
      float g = As[tid * ST + j];
      #pragma unroll
      for (int k = 0; k < WAYS; k++) a[k] += g * csh[k * NF + j];
    }
    #pragma unroll
    for (int k = 0; k < WAYS; k++) tsh[k * NF + tid] = a[k];
  }
  __syncthreads();

  // cross[k][l] = c_k . t_l  (25 tasks over 8 warps)
  for (int p = w; p < WAYS * WAYS; p += 8) {
    int k = p / WAYS, l = p % WAYS;
    float v = 0.f;
    for (int i = lane; i < NF; i += 32) v += csh[k * NF + i] * tsh[l * NF + i];
    v = wred(v);
    if (lane == 0) crs[k][l] = v;
  }
  __syncthreads();

  // dp, score, omega, mask
  if (tid < WAYS * WAYS) {
    int k = tid / WAYS, l = tid % WAYS;
    float d2 = fmaxf(crs[k][k] + crs[l][l] - 2.0f * crs[k][l], 0.0f);
    dp[k][l] = expf(-LAM * d2);
  }
  __syncthreads();
  if (tid < WAYS) {
    float p[WAYS], s = 0.f;
    #pragma unroll
    for (int k = 0; k < WAYS; k++) { p[k] = dp[tid][k] + 1e-12f; s += p[k]; }
    float H = 0.f;
    #pragma unroll
    for (int k = 0; k < WAYS; k++) { float q = p[k] / s; H -= q * logf(q); }
    score[tid] = H / logf(5.0f);
  }
  if (w == 0) {
    float part = 0.f;
    for (int i = lane; i < NF; i += 32) part += ent[i];
    part = wred(part);
    if (lane == 0) omega_s = part / 100.0f;
  }
  __syncthreads();
  if (tid < WAYS) maskv[tid] = (score[tid] < omega_s) ? 1.0f : 0.0f;
  __syncthreads();

  // fill proto entries of S and Zext proto rows
  if (tid < NF) {
    #pragma unroll
    for (int k = 0; k < WAYS; k++) {
      float v = maskv[k] * tsh[k * NF + tid];
      As[tid * ST + NF + k] = v;
      As[(NF + k) * ST + tid] = v;
    }
  }
  if (tid < WAYS * WAYS) {
    int k = tid / WAYS, l = tid % WAYS;
    As[(NF + k) * ST + NF + l] = maskv[k] * maskv[l] * crs[k][l];
    yv[NF + k][l] = maskv[k] * dp[k][l];
  }
  __syncthreads();

  // ---- graph transform ----
  if (tid < FROWS) {
    n2[tid] = (tid < NTOT) ? As[tid * ST + tid] : 0.f;
    rsum[tid] = 0.f;
  }
  __syncthreads();
  float acc[7][7];
  #pragma unroll
  for (int r = 0; r < 7; r++) {
    int gi = ti * 7 + r;
    #pragma unroll
    for (int c = 0; c < 7; c++) {
      int gj = tj * 7 + c;
      float wv = 0.f;
      if (gi < NTOT && gj < NTOT && gi != gj) {
        float d2 = fmaxf(n2[gi] + n2[gj] - 2.0f * As[gi * ST + gj], 0.0f);
        wv = expf(-LAM * d2);
      }
      acc[r][c] = wv;
    }
  }
  #pragma unroll
  for (int r = 0; r < 7; r++) {
    int gi = ti * 7 + r;
    float p = 0.f;
    #pragma unroll
    for (int c = 0; c < 7; c++) p += acc[r][c];
    if (gi < NTOT) atomicAdd(&rsum[gi], p);
  }
  __syncthreads();
  if (tid < FROWS) Dm[tid] = (tid < NTOT) ? (1.0f / sqrtf(rsum[tid])) : 0.f;
  __syncthreads();
  #pragma unroll
  for (int r = 0; r < 7; r++) {
    int gi = ti * 7 + r;
    float di = Dm[gi];
    #pragma unroll
    for (int c = 0; c < 7; c++) {
      int gj = tj * 7 + c;
      acc[r][c] = ((gi == gj) ? 1.0f : 0.0f) - ALPHA_ * di * acc[r][c] * Dm[gj];
    }
  }
  __syncthreads();

  // ---- register Cholesky ----
  for (int jt = 0; jt < 15; jt++) {
    #pragma unroll
    for (int jc = 0; jc < 7; jc++) {
      int j = jt * 7 + jc;
      int buf = j & 1;
      if (tid < FROWS) colbuf[buf][tid] = 0.f;
      if (ti == jt && tj == jt) {
        float pv = sqrtf(acc[jc][jc]);
        acc[jc][jc] = pv;
        sh_piv = pv;
      }
      __syncthreads();
      if (tj == jt) {
        float ip = 1.0f / sh_piv;
        #pragma unroll
        for (int r = 0; r < 7; r++) {
          int gi = ti * 7 + r;
          if (gi > j) { acc[r][jc] *= ip; colbuf[buf][gi] = acc[r][jc]; }
        }
      }
      __syncthreads();
      float rv[7], cv[7];
      #pragma unroll
      for (int r = 0; r < 7; r++) rv[r] = colbuf[buf][ti * 7 + r];
      #pragma unroll
      for (int c = 0; c < 7; c++) cv[c] = colbuf[buf][tj * 7 + c];
      #pragma unroll
      for (int r = 0; r < 7; r++)
        #pragma unroll
        for (int c = 0; c < 7; c++) acc[r][c] -= rv[r] * cv[c];
    }
  }
  __syncthreads();   // As dead; reuse as Lsh

  #pragma unroll
  for (int r = 0; r < 7; r++) {
    int gi = ti * 7 + r;
    #pragma unroll
    for (int c = 0; c < 7; c++) {
      int gj = tj * 7 + c;
      if (gi < NTOT && gj < NTOT && gj <= gi) Lsh[gi * ST + gj] = acc[r][c];
    }
  }
  __syncthreads();

  // ---- triangular solves: warp w owns RHS col w; shfl-broadcast sweep ----
  if (w < WAYS) {
    float rr[4], dinv[4];
    #pragma unroll
    for (int s = 0; s < 4; s++) {
      int row = lane + 32 * s;
      rr[s]   = (row < NTOT) ? yv[row][w] : 0.f;
      dinv[s] = (row < NTOT) ? (1.0f / Lsh[row * ST + row]) : 0.f;
    }
    for (int i = 0; i < NTOT; i++) {
      int s_i = i >> 5, src = i & 31;
      float yi = rr[s_i] * dinv[s_i];
      yi = __shfl_sync(0xffffffffu, yi, src);
      if (lane == src) rr[s_i] = yi;
      #pragma unroll
      for (int s = 0; s < 4; s++) {
        int row = lane + 32 * s;
        if (row > i && row < NTOT) rr[s] -= Lsh[row * ST + i] * yi;
      }
    }
    for (int i = NTOT - 1; i >= 0; i--) {
      int s_i = i >> 5, src = i & 31;
      float xi = rr[s_i] * dinv[s_i];
      xi = __shfl_sync(0xffffffffu, xi, src);
      if (lane == src) rr[s_i] = xi;
      #pragma unroll
      for (int s = 0; s < 4; s++) {
        int row = lane + 32 * s;
        if (row < i) rr[s] -= Lsh[i * ST + row] * xi;
      }
    }
    #pragma unroll
    for (int s = 0; s < 4; s++) {
      int row = lane + 32 * s;
      if (row < NTOT) yv[row][w] = rr[s];
    }
  }
  __syncthreads();

  for (int idx = tid; idx < NTOT * WAYS; idx += 256)
    ((float*)g_Z0[run])[idx] = ((const float*)yv)[idx];
}

// ---------------- KC2: sinkhorn2 pass-1, 1 warp per run ---------------------
__global__ __launch_bounds__(128) void kc2_kernel(const int* __restrict__ ys) {
  int tid = threadIdx.x, w = tid >> 5, lane = tid & 31;
  int run = blockIdx.x * 4 + w;
  const int* ysr = ys + run * NSUP;
  float P[4][WAYS];
  #pragma unroll
  for (int s = 0; s < 4; s++) {
    int row = lane + 32 * s;
    #pragma unroll
    for (int k = 0; k < WAYS; k++) P[s][k] = (row < NTOT) ? g_Z0[run][row][k] : 0.f;
  }
  int cls = (lane < NSUP) ? ysr[lane] : 0;
  int b = sink_pass1<4, NTOT, true>(P, 21.0f, lane, cls);
  #pragma unroll
  for (int s = 0; s < 4; s++) {
    int row = lane + 32 * s;
    if (row < NTOT)
      #pragma unroll
      for (int k = 0; k < WAYS; k++) g_Z0[run][row][k] = P[s][k];
  }
  if (lane == 0) g_b2run[run] = b;
}

// ---------------- KD: 1 warp per run: replay sinkhorn2, argmax, accuracy ----
__global__ __launch_bounds__(128) void kd_kernel(const int* __restrict__ ys,
                                                 const int* __restrict__ yq,
                                                 float* __restrict__ out) {
  int tid = threadIdx.x, w = tid >> 5, lane = tid & 31;
  int run = blockIdx.x * 4 + w;
  const int* ysr = ys + run * NSUP;
  float P[4][WAYS];
  #pragma unroll
  for (int s = 0; s < 4; s++) {
    int row = lane + 32 * s;
    #pragma unroll
    for (int k = 0; k < WAYS; k++) P[s][k] = (row < NTOT) ? g_Z0[run][row][k] : 0.f;
  }
  int cls = (lane < NSUP) ? ysr[lane] : 0;
  int m = 0;
  for (int i = lane; i < RUNS; i += 32) m = max(m, g_b2run[i]);
  m = __reduce_max_sync(0xffffffffu, m);
  sink_replay<4, NTOT, true>(P, 21.0f, lane, cls, m - g_b2run[run]);

  int cnt = 0;
  #pragma unroll
  for (int s = 0; s < 4; s++) {
    int row = lane + 32 * s;
    if (row >= NSUP && row < NF) {
      float best = P[s][0]; int bi = 0;
      #pragma unroll
      for (int k = 1; k < WAYS; k++)
        if (P[s][k] > best) { best = P[s][k]; bi = k; }
      if (bi == yq[run * NQ + (row - NSUP)]) cnt++;
    }
  }
  #pragma unroll
  for (int o = 16; o; o >>= 1) cnt += __shfl_xor_sync(0xffffffffu, cnt, o);
  if (lane == 0) out[run] = (float)cnt / 75.0f;
}

// ---------------------------------------------------------------------------
extern "C" void kernel_launch(void* const* d_in, const int* in_sizes, int n_in,
                              void* d_out, int out_size) {
  const float* xs = (const float*)d_in[0];
  const float* xq = (const float*)d_in[1];
  const int*   ys = (const int*)d_in[2];
  const int*   yq = (const int*)d_in[3];
  float* out = (float*)d_out;

  cudaFuncSetAttribute(kgram_kernel, cudaFuncAttributeMaxDynamicSharedMemorySize,
                       KG_SMEM);
  cudaFuncSetAttribute(kea_kernel, cudaFuncAttributeMaxDynamicSharedMemorySize,
                       KG_SMEM);
  cudaFuncSetAttribute(kb01_kernel, cudaFuncAttributeMaxDynamicSharedMemorySize,
                       KG_SMEM);
  cudaFuncSetAttribute(kb2_kernel, cudaFuncAttributeMaxDynamicSharedMemorySize,
                       KB2_SMEM);

  kgram_kernel<<<RUNS, 256, KG_SMEM>>>(xs, xq);
  kea_kernel<<<RUNS, 160, KG_SMEM>>>(ys);
  kb01_kernel<<<RUNS, 160, KG_SMEM>>>(ys, 0);
  kb01_kernel<<<RUNS, 160, KG_SMEM>>>(ys, 1);
  kb2_kernel<<<RUNS, 256, KB2_SMEM>>>(ys);
  kc2_kernel<<<RUNS / 4, 128>>>(ys);
  kd_kernel<<<RUNS / 4, 128>>>(ys, yq, out);
}

// round 13
// speedup vs baseline: 2.2075x; 1.1440x over previous
#include <cuda_runtime.h>
#include <math.h>
#include <stdint.h>

#define RUNS 512
#define WAYS 5
#define SHOT 5
#define NSUP 25
#define NQ   75
#define NF   100
#define NTOT 105
#define DIM  640
#define LAM  10.0f
#define ALPHA_ 0.7f
#define EPSV 1e-3f
#define MAXIT 1000

#define GST 101        // shared G stride
#define ST  107        // shared S stride in kb2

// ---------------- device scratch (static: no allocations allowed) ----------
__device__ float g_G[RUNS][NF * NF];        // feature Gram (20.5 MB)
__device__ float g_c[RUNS][WAYS * NF];      // proto coefficients [k*100+i]
__device__ float g_P1[RUNS][NQ][WAYS];      // sinkhorn1 state after epoch-2 pass-1
__device__ int   g_b1A[RUNS];               // per-run body counts (per phase)
__device__ int   g_b1B[RUNS];
__device__ int   g_b1C[RUNS];
__device__ float g_Z0[RUNS][NTOT][WAYS];    // solved Z
__device__ int   g_b2run[RUNS];
__device__ int   g_syncA;                   // grid-barrier counter (kmain)
__device__ int   g_syncB;                   // grid-barrier counter (kcd)

__device__ __forceinline__ float wred(float v) {
  #pragma unroll
  for (int o = 16; o; o >>= 1) v += __shfl_down_sync(0xffffffffu, v, o);
  return v;
}
__device__ __forceinline__ float wsum_x(float v) {
  #pragma unroll
  for (int o = 16; o; o >>= 1) v += __shfl_xor_sync(0xffffffffu, v, o);
  return v;
}
__device__ __forceinline__ float wmax_x(float v) {
  #pragma unroll
  for (int o = 16; o; o >>= 1) v = fmaxf(v, __shfl_xor_sync(0xffffffffu, v, o));
  return v;
}
__device__ __forceinline__ float fdiv(float a, float b) { return __fdividef(a, b); }

// Monotonic grid barrier: every call site with the same counter must use the
// same grid size N. Counter never resets; target = (my/N + 1)*N is correct
// across graph replays and multiple barriers per launch.
__device__ __forceinline__ void grid_barrier(int* cnt, int n, int tid) {
  __threadfence();
  __syncthreads();
  if (tid == 0) {
    int my = atomicAdd(cnt, 1);
    int target = (my / n + 1) * n;
    volatile int* vc = (volatile int*)cnt;
    while (*vc < target) { }
  }
  __syncthreads();
}

// ---- single-warp register sinkhorn: pass-1 (count bodies to own converge) --
template<int NR, int NROWS, bool LAB>
__device__ __forceinline__ int sink_pass1(float (&P)[NR][WAYS], float ctot,
                                          int lane, int cls) {
  float u[NR];
  #pragma unroll
  for (int s = 0; s < NR; s++) u[s] = 0.f;
  int b = 0;
  for (;;) {
    float rs[NR];
    float d = 0.f;
    #pragma unroll
    for (int s = 0; s < NR; s++) {
      rs[s] = P[s][0] + P[s][1] + P[s][2] + P[s][3] + P[s][4];
      if (lane + 32 * s < NROWS) d = fmaxf(d, fabsf(u[s] - rs[s]));
    }
    float delta = wmax_x(d);
    float t[NR][WAYS];
    float cp[WAYS] = {0.f, 0.f, 0.f, 0.f, 0.f};
    #pragma unroll
    for (int s = 0; s < NR; s++) {
      float inv = (lane + 32 * s < NROWS) ? fdiv(1.0f, rs[s]) : 0.f;
      #pragma unroll
      for (int k = 0; k < WAYS; k++) { t[s][k] = P[s][k] * inv; cp[k] += t[s][k]; }
    }
    float f[WAYS];
    #pragma unroll
    for (int k = 0; k < WAYS; k++) f[k] = fdiv(ctot, wsum_x(cp[k]));
    #pragma unroll
    for (int s = 0; s < NR; s++)
      #pragma unroll
      for (int k = 0; k < WAYS; k++) t[s][k] *= f[k];
    if (LAB && lane < NSUP) {
      #pragma unroll
      for (int k = 0; k < WAYS; k++) t[0][k] = (k == cls) ? 1.f : 0.f;
    }
    if (!(delta > EPSV && b < MAXIT)) break;
    #pragma unroll
    for (int s = 0; s < NR; s++) {
      u[s] = rs[s];
      #pragma unroll
      for (int k = 0; k < WAYS; k++) P[s][k] = t[s][k];
    }
    b++;
  }
  return b;
}

// ---- single-warp register sinkhorn: replay exactly `iters` bodies ----------
template<int NR, int NROWS, bool LAB>
__device__ __forceinline__ void sink_replay(float (&P)[NR][WAYS], float ctot,
                                            int lane, int cls, int iters) {
  for (int it = 0; it < iters; it++) {
    float cp[WAYS] = {0.f, 0.f, 0.f, 0.f, 0.f};
    #pragma unroll
    for (int s = 0; s < NR; s++) {
      float rs = P[s][0] + P[s][1] + P[s][2] + P[s][3] + P[s][4];
      float inv = (lane + 32 * s < NROWS) ? fdiv(1.0f, rs) : 0.f;
      #pragma unroll
      for (int k = 0; k < WAYS; k++) { P[s][k] *= inv; cp[k] += P[s][k]; }
    }
    float f[WAYS];
    #pragma unroll
    for (int k = 0; k < WAYS; k++) f[k] = fdiv(ctot, wsum_x(cp[k]));
    #pragma unroll
    for (int s = 0; s < NR; s++)
      #pragma unroll
      for (int k = 0; k < WAYS; k++) P[s][k] *= f[k];
    if (LAB && lane < NSUP) {
      #pragma unroll
      for (int k = 0; k < WAYS; k++) P[0][k] = (k == cls) ? 1.f : 0.f;
    }
  }
}

// ==================== KMAIN: Gram + epochs 0,1 (grid-barriered) =============
#define GNT 17                        // ceil(100/6) tile rows
#define GNTRI (GNT * (GNT + 1) / 2)   // 153 triangular tiles (<=160 threads)
#define GFR 102
#define GFPAD 66
#define KM_SMEM (NF * GST * 4)        // 40,400B dynamic (Fsh 26,928B aliased)

__global__ __launch_bounds__(160, 4) void kmain_kernel(const float* __restrict__ xs,
                                                       const float* __restrict__ xq,
                                                       const int* __restrict__ ys) {
  extern __shared__ float sm[];
  float* Fsh = sm;                    // during Gram
  float* Gs  = sm;                    // after (stride GST)
  __shared__ float csh[WAYS * NF];
  __shared__ float tsh[WAYS * NF];
  __shared__ float Psh[NQ][WAYS];
  __shared__ float Z[NF][WAYS];
  __shared__ float ent[NF];
  __shared__ float cs[WAYS];
  __shared__ float pn2[WAYS];
  __shared__ int ysh[NSUP];
  __shared__ int bsh;
  int run = blockIdx.x, tid = threadIdx.x;
  int w = tid >> 5, lane = tid & 31;
  const float* xsr = xs + (size_t)run * NSUP * DIM;
  const float* xqr = xq + (size_t)run * NQ * DIM;
  const int* ysr = ys + run * NSUP;

  if (tid < NSUP) ysh[tid] = ysr[tid];

  // ---------------- Phase A: Gram ----------------
  bool act = tid < GNTRI;
  int tix = 0, tjx = 0;
  if (act) {
    tix = (int)((sqrtf(8.0f * (float)tid + 1.0f) - 1.0f) * 0.5f);
    while ((tix + 1) * (tix + 2) / 2 <= tid) tix++;
    while (tix * (tix + 1) / 2 > tid) tix--;
    tjx = tid - tix * (tix + 1) / 2;
  }

  unsigned long long acc2[6][6];
  #pragma unroll
  for (int r = 0; r < 6; r++)
    #pragma unroll
    for (int c = 0; c < 6; c++) acc2[r][c] = 0ull;

  for (int c0 = 0; c0 < DIM; c0 += 64) {
    __syncthreads();
    for (int idx = tid; idx < GFR * 32; idx += 160) {
      int r = idx >> 5, q = idx & 31;
      float2 v = make_float2(0.f, 0.f);
      int c = c0 + 2 * q;
      if (r < NSUP)    v = *(const float2*)&xsr[r * DIM + c];
      else if (r < NF) v = *(const float2*)&xqr[(r - NSUP) * DIM + c];
      *(float2*)&Fsh[r * GFPAD + 2 * q] = v;
    }
    __syncthreads();
    if (act) {
      #pragma unroll 4
      for (int dd = 0; dd < 64; dd += 2) {
        unsigned long long a2[6], b2[6];
        #pragma unroll
        for (int r = 0; r < 6; r++)
          a2[r] = *(const unsigned long long*)&Fsh[(tix * 6 + r) * GFPAD + dd];
        #pragma unroll
        for (int c = 0; c < 6; c++)
          b2[c] = *(const unsigned long long*)&Fsh[(tjx * 6 + c) * GFPAD + dd];
        #pragma unroll
        for (int r = 0; r < 6; r++)
          #pragma unroll
          for (int c = 0; c < 6; c++)
            asm("fma.rn.f32x2 %0, %1, %2, %0;"
                : "+l"(acc2[r][c]) : "l"(a2[r]), "l"(b2[c]));
      }
    }
  }
  __syncthreads();   // Fsh dead; reuse as Gs

  if (act) {
    #pragma unroll
    for (int r = 0; r < 6; r++) {
      int gi = tix * 6 + r;
      #pragma unroll
      for (int c = 0; c < 6; c++) {
        int gj = tjx * 6 + c;
        if (gi < NF && gj < NF) {
          float2 v2 = *(float2*)&acc2[r][c];
          float sv = v2.x + v2.y;
          Gs[gi * GST + gj] = sv;
          if (tix > tjx) Gs[gj * GST + gi] = sv;
        }
      }
    }
  }
  __syncthreads();
  // store G for kb2 (coalesced)
  for (int idx = tid; idx < NF * NF; idx += 160) {
    int i = idx / NF, j = idx % NF;
    g_G[run][idx] = Gs[i * GST + j];
  }

  // ---------------- Phase A: epoch-0 Pq + pass-1 ----------------
  // c0 in shared
  for (int idx = tid; idx < WAYS * NF; idx += 160) {
    int k = idx / NF, i = idx % NF;
    csh[idx] = (i < NSUP && ysh[i] == k) ? 0.2f : 0.f;
  }
  // t_k[i] = 0.2 * sum_{i' in class k} G[i][i']
  if (tid < NF) {
    float gv[NSUP];
    #pragma unroll
    for (int i2 = 0; i2 < NSUP; i2++) gv[i2] = Gs[tid * GST + i2];
    #pragma unroll
    for (int k = 0; k < WAYS; k++) {
      float s = 0.f;
      #pragma unroll
      for (int i2 = 0; i2 < NSUP; i2++) s += (ysh[i2] == k) ? gv[i2] : 0.f;
      tsh[k * NF + tid] = 0.2f * s;
    }
  }
  __syncthreads();
  { // pn[k] = 0.2 * sum_{i in class k} t_k[i]
    if (w < WAYS) {
      float v = (lane < NSUP && ysh[lane] == w) ? tsh[w * NF + lane] : 0.f;
      v = wred(v);
      if (lane == 0) pn2[w] = 0.2f * v;
    }
  }
  __syncthreads();
  if (tid < NQ) {
    int row = NSUP + tid;
    float nq2 = Gs[row * GST + row];
    #pragma unroll
    for (int k = 0; k < WAYS; k++) {
      float d2 = fmaxf(nq2 + pn2[k] - 2.0f * tsh[k * NF + row], 0.0f);
      Psh[tid][k] = expf(-LAM * d2);
    }
  }
  __syncthreads();
  if (tid < 32) {
    float P[3][WAYS];
    #pragma unroll
    for (int s = 0; s < 3; s++) {
      int row = lane + 32 * s;
      #pragma unroll
      for (int k = 0; k < WAYS; k++) P[s][k] = (row < NQ) ? Psh[row][k] : 0.f;
    }
    int b = sink_pass1<3, NQ, false>(P, 15.0f, lane, 0);
    #pragma unroll
    for (int s = 0; s < 3; s++) {
      int row = lane + 32 * s;
      if (row < NQ)
        #pragma unroll
        for (int k = 0; k < WAYS; k++) Psh[row][k] = P[s][k];
    }
    if (lane == 0) { bsh = b; g_b1A[run] = b; }
  }

  // ================= epochs 0 and 1 =================
  #pragma unroll 1
  for (int epoch = 0; epoch < 2; epoch++) {
    grid_barrier(&g_syncA, RUNS, tid);

    const int* rb = (epoch == 0) ? g_b1A : g_b1B;
    if (tid < 32) {  // replay to global max (Psh holds pass-1 state)
      float P[3][WAYS];
      #pragma unroll
      for (int s = 0; s < 3; s++) {
        int row = lane + 32 * s;
        #pragma unroll
        for (int k = 0; k < WAYS; k++) P[s][k] = (row < NQ) ? Psh[row][k] : 0.f;
      }
      int m = 0;
      for (int i = lane; i < RUNS; i += 32) m = max(m, __ldcg(&rb[i]));
      m = __reduce_max_sync(0xffffffffu, m);
      sink_replay<3, NQ, false>(P, 15.0f, lane, 0, m - bsh);
      #pragma unroll
      for (int s = 0; s < 3; s++) {
        int row = lane + 32 * s;
        if (row < NQ)
          #pragma unroll
          for (int k = 0; k < WAYS; k++) Psh[row][k] = P[s][k];
      }
    }
    __syncthreads();

    // Z = [onehot; Pq]
    for (int idx = tid; idx < NF * WAYS; idx += 160) {
      int i = idx / WAYS, k = idx % WAYS;
      Z[i][k] = (i < NSUP) ? ((ysh[i] == k) ? 1.0f : 0.0f) : Psh[i - NSUP][k];
    }
    __syncthreads();
    if (tid < NF) {
      float p[WAYS], s = 0.f;
      #pragma unroll
      for (int k = 0; k < WAYS; k++) { p[k] = Z[tid][k] + 1e-12f; s += p[k]; }
      float H = 0.f;
      #pragma unroll
      for (int k = 0; k < WAYS; k++) { float q = p[k] / s; H -= q * logf(q); }
      ent[tid] = H / logf(5.0f);
    }
    __syncthreads();
    for (int idx = tid; idx < NF * WAYS; idx += 160)
      ((float*)Z)[idx] *= (1.0f - ent[idx / WAYS]);
    __syncthreads();
    if (w < WAYS) {
      float part = 0.f;
      for (int i = lane; i < NF; i += 32) part += Z[i][w];
      part = wred(part);
      if (lane == 0) cs[w] = part;
    }
    __syncthreads();

    // c update (shared-resident); write g_c on the final epoch for kb2
    for (int idx = tid; idx < WAYS * NF; idx += 160) {
      int k = idx / NF, i = idx % NF;
      float v = 0.4f * csh[idx] + 0.6f * Z[i][k] / cs[k];
      csh[idx] = v;
      if (epoch == 1) g_c[run][idx] = v;
    }
    __syncthreads();

    // t_k = G c_k
    if (tid < NF) {
      float a[WAYS] = {0.f, 0.f, 0.f, 0.f, 0.f};
      for (int j = 0; j < NF; j++) {
        float g = Gs[tid * GST + j];
        #pragma unroll
        for (int k = 0; k < WAYS; k++) a[k] += g * csh[k * NF + j];
      }
      #pragma unroll
      for (int k = 0; k < WAYS; k++) tsh[k * NF + tid] = a[k];
    }
    __syncthreads();
    if (w < WAYS) { // pn[k] = c_k . t_k
      float v = 0.f;
      for (int i = lane; i < NF; i += 32) v += csh[w * NF + i] * tsh[w * NF + i];
      v = wred(v);
      if (lane == 0) pn2[w] = v;
    }
    __syncthreads();
    if (tid < NQ) {
      int row = NSUP + tid;
      float nq2 = Gs[row * GST + row];
      #pragma unroll
      for (int k = 0; k < WAYS; k++) {
        float d2 = fmaxf(nq2 + pn2[k] - 2.0f * tsh[k * NF + row], 0.0f);
        Psh[tid][k] = expf(-LAM * d2);
      }
    }
    __syncthreads();
    if (tid < 32) {
      float P[3][WAYS];
      #pragma unroll
      for (int s = 0; s < 3; s++) {
        int row = lane + 32 * s;
        #pragma unroll
        for (int k = 0; k < WAYS; k++) P[s][k] = (row < NQ) ? Psh[row][k] : 0.f;
      }
      int b = sink_pass1<3, NQ, false>(P, 15.0f, lane, 0);
      #pragma unroll
      for (int s = 0; s < 3; s++) {
        int row = lane + 32 * s;
        if (row < NQ) {
          #pragma unroll
          for (int k = 0; k < WAYS; k++) {
            Psh[row][k] = P[s][k];
            if (epoch == 1) g_P1[run][row][k] = P[s][k];
          }
        }
      }
      if (lane == 0) {
        bsh = b;
        if (epoch == 0) g_b1B[run] = b; else g_b1C[run] = b;
      }
    }
    __syncthreads();
  }
}

// ---- KB2 (e=2): replay, blend, build S from G, graph, Cholesky, solves -----
#define FROWS 112
#define KB2_SMEM (NTOT * ST * 4)   // 44,940B

__global__ __launch_bounds__(256, 2) void kb2_kernel(const int* __restrict__ ys) {
  extern __shared__ float sm[];
  float* As  = sm;                  // [105][ST]: G + proto rows -> W -> (L)
  float* Lsh = sm;
  __shared__ float csh[WAYS * NF];
  __shared__ float tsh[WAYS * NF];
  __shared__ float Psh[NQ][WAYS];
  __shared__ float ent[NF];
  __shared__ float cs[WAYS];
  __shared__ float crs[WAYS][WAYS];
  __shared__ float dp[WAYS][WAYS];
  __shared__ float score[WAYS], maskv[WAYS];
  __shared__ float omega_s;
  __shared__ int ysh[NSUP];
  __shared__ float n2[FROWS];
  __shared__ float rsum[FROWS];
  __shared__ float Dm[FROWS];
  __shared__ float colbuf[2][FROWS];
  __shared__ float sh_piv;
  __shared__ float yv[NTOT][WAYS];

  int run = blockIdx.x, tid = threadIdx.x;
  int ti = tid >> 4, tj = tid & 15;
  int w = tid >> 5, lane = tid & 31;
  const int* ysr = ys + run * NSUP;

  if (tid < 32) {  // warp 0: replay sinkhorn1 epoch-2 (counts in g_b1C)
    float P[3][WAYS];
    #pragma unroll
    for (int s = 0; s < 3; s++) {
      int row = lane + 32 * s;
      #pragma unroll
      for (int k = 0; k < WAYS; k++) P[s][k] = (row < NQ) ? g_P1[run][row][k] : 0.f;
    }
    int m = 0;
    for (int i = lane; i < RUNS; i += 32) m = max(m, g_b1C[i]);
    m = __reduce_max_sync(0xffffffffu, m);
    sink_replay<3, NQ, false>(P, 15.0f, lane, 0, m - g_b1C[run]);
    #pragma unroll
    for (int s = 0; s < 3; s++) {
      int row = lane + 32 * s;
      if (row < NQ)
        #pragma unroll
        for (int k = 0; k < WAYS; k++) Psh[row][k] = P[s][k];
    }
  } else {
    int t7 = tid - 32;   // 0..223
    for (int idx = t7; idx < NF * NF; idx += 224) {
      int i = idx / NF, j = idx % NF;
      As[i * ST + j] = g_G[run][idx];
    }
    for (int idx = t7; idx < WAYS * NF; idx += 224) csh[idx] = g_c[run][idx];
    if (t7 < NSUP) ysh[t7] = ysr[t7];
  }
  __syncthreads();

  // Z (into yv rows 0..99), entropy, weight, cs
  for (int idx = tid; idx < NF * WAYS; idx += 256) {
    int i = idx / WAYS, k = idx % WAYS;
    yv[i][k] = (i < NSUP) ? ((ysh[i] == k) ? 1.0f : 0.0f) : Psh[i - NSUP][k];
  }
  __syncthreads();
  if (tid < NF) {
    float p[WAYS], s = 0.f;
    #pragma unroll
    for (int k = 0; k < WAYS; k++) { p[k] = yv[tid][k] + 1e-12f; s += p[k]; }
    float H = 0.f;
    #pragma unroll
    for (int k = 0; k < WAYS; k++) { float q = p[k] / s; H -= q * logf(q); }
    ent[tid] = H / logf(5.0f);
  }
  __syncthreads();
  for (int idx = tid; idx < NF * WAYS; idx += 256)
    ((float*)yv)[idx] *= (1.0f - ent[idx / WAYS]);
  __syncthreads();
  if (w < WAYS) {
    float part = 0.f;
    for (int i = lane; i < NF; i += 32) part += yv[i][w];
    part = wred(part);
    if (lane == 0) cs[w] = part;
  }
  __syncthreads();

  for (int idx = tid; idx < WAYS * NF; idx += 256) {
    int k = idx / NF, i = idx % NF;
    csh[idx] = 0.4f * csh[idx] + 0.6f * yv[i][k] / cs[k];
  }
  __syncthreads();

  // t_k = G c_k
  if (tid < NF) {
    float a[WAYS] = {0.f, 0.f, 0.f, 0.f, 0.f};
    for (int j = 0; j < NF; j++) {
      float g = As[tid * ST + j];
      #pragma unroll
      for (int k = 0; k < WAYS; k++) a[k] += g * csh[k * NF + j];
    }
    #pragma unroll
    for (int k = 0; k < WAYS; k++) tsh[k * NF + tid] = a[k];
  }
  __syncthreads();

  for (int p = w; p < WAYS * WAYS; p += 8) {
    int k = p / WAYS, l = p % WAYS;
    float v = 0.f;
    for (int i = lane; i < NF; i += 32) v += csh[k * NF + i] * tsh[l * NF + i];
    v = wred(v);
    if (lane == 0) crs[k][l] = v;
  }
  __syncthreads();

  if (tid < WAYS * WAYS) {
    int k = tid / WAYS, l = tid % WAYS;
    float d2 = fmaxf(crs[k][k] + crs[l][l] - 2.0f * crs[k][l], 0.0f);
    dp[k][l] = expf(-LAM * d2);
  }
  __syncthreads();
  if (tid < WAYS) {
    float p[WAYS], s = 0.f;
    #pragma unroll
    for (int k = 0; k < WAYS; k++) { p[k] = dp[tid][k] + 1e-12f; s += p[k]; }
    float H = 0.f;
    #pragma unroll
    for (int k = 0; k < WAYS; k++) { float q = p[k] / s; H -= q * logf(q); }
    score[tid] = H / logf(5.0f);
  }
  if (w == 0) {
    float part = 0.f;
    for (int i = lane; i < NF; i += 32) part += ent[i];
    part = wred(part);
    if (lane == 0) omega_s = part / 100.0f;
  }
  __syncthreads();
  if (tid < WAYS) maskv[tid] = (score[tid] < omega_s) ? 1.0f : 0.0f;
  __syncthreads();

  if (tid < NF) {
    #pragma unroll
    for (int k = 0; k < WAYS; k++) {
      float v = maskv[k] * tsh[k * NF + tid];
      As[tid * ST + NF + k] = v;
      As[(NF + k) * ST + tid] = v;
    }
  }
  if (tid < WAYS * WAYS) {
    int k = tid / WAYS, l = tid % WAYS;
    As[(NF + k) * ST + NF + l] = maskv[k] * maskv[l] * crs[k][l];
    yv[NF + k][l] = maskv[k] * dp[k][l];
  }
  __syncthreads();

  // ---- graph transform ----
  if (tid < FROWS) {
    n2[tid] = (tid < NTOT) ? As[tid * ST + tid] : 0.f;
    rsum[tid] = 0.f;
  }
  __syncthreads();
  float acc[7][7];
  #pragma unroll
  for (int r = 0; r < 7; r++) {
    int gi = ti * 7 + r;
    #pragma unroll
    for (int c = 0; c < 7; c++) {
      int gj = tj * 7 + c;
      float wv = 0.f;
      if (gi < NTOT && gj < NTOT && gi != gj) {
        float d2 = fmaxf(n2[gi] + n2[gj] - 2.0f * As[gi * ST + gj], 0.0f);
        wv = expf(-LAM * d2);
      }
      acc[r][c] = wv;
    }
  }
  #pragma unroll
  for (int r = 0; r < 7; r++) {
    int gi = ti * 7 + r;
    float p = 0.f;
    #pragma unroll
    for (int c = 0; c < 7; c++) p += acc[r][c];
    if (gi < NTOT) atomicAdd(&rsum[gi], p);
  }
  __syncthreads();
  if (tid < FROWS) Dm[tid] = (tid < NTOT) ? (1.0f / sqrtf(rsum[tid])) : 0.f;
  __syncthreads();
  #pragma unroll
  for (int r = 0; r < 7; r++) {
    int gi = ti * 7 + r;
    float di = Dm[gi];
    #pragma unroll
    for (int c = 0; c < 7; c++) {
      int gj = tj * 7 + c;
      acc[r][c] = ((gi == gj) ? 1.0f : 0.0f) - ALPHA_ * di * acc[r][c] * Dm[gj];
    }
  }
  __syncthreads();

  // ---- register Cholesky ----
  for (int jt = 0; jt < 15; jt++) {
    #pragma unroll
    for (int jc = 0; jc < 7; jc++) {
      int j = jt * 7 + jc;
      int buf = j & 1;
      if (tid < FROWS) colbuf[buf][tid] = 0.f;
      if (ti == jt && tj == jt) {
        float pv = sqrtf(acc[jc][jc]);
        acc[jc][jc] = pv;
        sh_piv = pv;
      }
      __syncthreads();
      if (tj == jt) {
        float ip = 1.0f / sh_piv;
        #pragma unroll
        for (int r = 0; r < 7; r++) {
          int gi = ti * 7 + r;
          if (gi > j) { acc[r][jc] *= ip; colbuf[buf][gi] = acc[r][jc]; }
        }
      }
      __syncthreads();
      float rv[7], cv[7];
      #pragma unroll
      for (int r = 0; r < 7; r++) rv[r] = colbuf[buf][ti * 7 + r];
      #pragma unroll
      for (int c = 0; c < 7; c++) cv[c] = colbuf[buf][tj * 7 + c];
      #pragma unroll
      for (int r = 0; r < 7; r++)
        #pragma unroll
        for (int c = 0; c < 7; c++) acc[r][c] -= rv[r] * cv[c];
    }
  }
  __syncthreads();   // As dead; reuse as Lsh

  #pragma unroll
  for (int r = 0; r < 7; r++) {
    int gi = ti * 7 + r;
    #pragma unroll
    for (int c = 0; c < 7; c++) {
      int gj = tj * 7 + c;
      if (gi < NTOT && gj < NTOT && gj <= gi) Lsh[gi * ST + gj] = acc[r][c];
    }
  }
  __syncthreads();

  // ---- triangular solves: warp w owns RHS col w; shfl-broadcast sweep ----
  if (w < WAYS) {
    float rr[4], dinv[4];
    #pragma unroll
    for (int s = 0; s < 4; s++) {
      int row = lane + 32 * s;
      rr[s]   = (row < NTOT) ? yv[row][w] : 0.f;
      dinv[s] = (row < NTOT) ? (1.0f / Lsh[row * ST + row]) : 0.f;
    }
    for (int i = 0; i < NTOT; i++) {
      int s_i = i >> 5, src = i & 31;
      float yi = rr[s_i] * dinv[s_i];
      yi = __shfl_sync(0xffffffffu, yi, src);
      if (lane == src) rr[s_i] = yi;
      #pragma unroll
      for (int s = 0; s < 4; s++) {
        int row = lane + 32 * s;
        if (row > i && row < NTOT) rr[s] -= Lsh[row * ST + i] * yi;
      }
    }
    for (int i = NTOT - 1; i >= 0; i--) {
      int s_i = i >> 5, src = i & 31;
      float xi = rr[s_i] * dinv[s_i];
      xi = __shfl_sync(0xffffffffu, xi, src);
      if (lane == src) rr[s_i] = xi;
      #pragma unroll
      for (int s = 0; s < 4; s++) {
        int row = lane + 32 * s;
        if (row < i) rr[s] -= Lsh[i * ST + row] * xi;
      }
    }
    #pragma unroll
    for (int s = 0; s < 4; s++) {
      int row = lane + 32 * s;
      if (row < NTOT) yv[row][w] = rr[s];
    }
  }
  __syncthreads();

  for (int idx = tid; idx < NTOT * WAYS; idx += 256)
    ((float*)g_Z0[run])[idx] = ((const float*)yv)[idx];
}

// ---- KCD: sinkhorn2 pass-1 + grid barrier + replay + argmax (merged) -------
#define KCD_BLOCKS (RUNS / 4)

__global__ __launch_bounds__(128) void kcd_kernel(const int* __restrict__ ys,
                                                  const int* __restrict__ yq,
                                                  float* __restrict__ out) {
  int tid = threadIdx.x, w = tid >> 5, lane = tid & 31;
  int run = blockIdx.x * 4 + w;
  const int* ysr = ys + run * NSUP;
  float P[4][WAYS];
  #pragma unroll
  for (int s = 0; s < 4; s++) {
    int row = lane + 32 * s;
    #pragma unroll
    for (int k = 0; k < WAYS; k++) P[s][k] = (row < NTOT) ? g_Z0[run][row][k] : 0.f;
  }
  int cls = (lane < NSUP) ? ysr[lane] : 0;
  int b = sink_pass1<4, NTOT, true>(P, 21.0f, lane, cls);
  if (lane == 0) g_b2run[run] = b;

  grid_barrier(&g_syncB, KCD_BLOCKS, tid);   // 128 blocks, all resident

  int m = 0;
  for (int i = lane; i < RUNS; i += 32) m = max(m, __ldcg(&g_b2run[i]));
  m = __reduce_max_sync(0xffffffffu, m);
  sink_replay<4, NTOT, true>(P, 21.0f, lane, cls, m - b);

  int cnt = 0;
  #pragma unroll
  for (int s = 0; s < 4; s++) {
    int row = lane + 32 * s;
    if (row >= NSUP && row < NF) {
      float best = P[s][0]; int bi = 0;
      #pragma unroll
      for (int k = 1; k < WAYS; k++)
        if (P[s][k] > best) { best = P[s][k]; bi = k; }
      if (bi == yq[run * NQ + (row - NSUP)]) cnt++;
    }
  }
  #pragma unroll
  for (int o = 16; o; o >>= 1) cnt += __shfl_xor_sync(0xffffffffu, cnt, o);
  if (lane == 0) out[run] = (float)cnt / 75.0f;
}

// ---------------------------------------------------------------------------
extern "C" void kernel_launch(void* const* d_in, const int* in_sizes, int n_in,
                              void* d_out, int out_size) {
  const float* xs = (const float*)d_in[0];
  const float* xq = (const float*)d_in[1];
  const int*   ys = (const int*)d_in[2];
  const int*   yq = (const int*)d_in[3];
  float* out = (float*)d_out;

  cudaFuncSetAttribute(kmain_kernel, cudaFuncAttributeMaxDynamicSharedMemorySize,
                       KM_SMEM);
  cudaFuncSetAttribute(kb2_kernel, cudaFuncAttributeMaxDynamicSharedMemorySize,
                       KB2_SMEM);

  kmain_kernel<<<RUNS, 160, KM_SMEM>>>(xs, xq, ys);
  kb2_kernel<<<RUNS, 256, KB2_SMEM>>>(ys);
  kcd_kernel<<<KCD_BLOCKS, 128>>>(ys, yq, out);
}